// round 1
// baseline (speedup 1.0000x reference)
#include <cuda_runtime.h>

#define TE 8
#define NODES_MAX 50000

typedef unsigned long long ull;

// scratch for edge-message aggregation (allocation-free rule: __device__ globals)
__device__ float g_agg_s[(size_t)NODES_MAX * 64];
__device__ float g_agg_v[(size_t)NODES_MAX * 192];

__device__ __forceinline__ ull ffma2(ull a, ull b, ull c) {
  ull d;
  asm("fma.rn.f32x2 %0, %1, %2, %3;" : "=l"(d) : "l"(a), "l"(b), "l"(c));
  return d;
}
__device__ __forceinline__ ull pack2(float x) {
  ull d;
  asm("mov.b64 %0, {%1, %1};" : "=l"(d) : "f"(x));
  return d;
}
__device__ __forceinline__ void upk8(const ull* a, float* f) {
#pragma unroll
  for (int j = 0; j < 4; j++) {
    f[2 * j]     = __int_as_float((int)(unsigned)(a[j] & 0xffffffffull));
    f[2 * j + 1] = __int_as_float((int)(unsigned)(a[j] >> 32));
  }
}
__device__ __forceinline__ float sigm(float x) { return 1.0f / (1.0f + __expf(-x)); }

#define RSQRT3 0.5773502692f
#define INV1   0.0622573010f   // 1/sqrt(258)
#define INV2   0.0883883476f   // 1/sqrt(128)
#define INV0   0.0625f         // 1/sqrt(256)
#define INVU   0.0883883476f   // 1/sqrt(128)

// accumulate 8 packed-pair lanes: A[j] += row[2j..2j+1] * w2
#define ACC4(arrRow, w2, A) do {                                               \
    ulonglong2 _r0 = *reinterpret_cast<const ulonglong2*>(arrRow);             \
    ulonglong2 _r1 = *reinterpret_cast<const ulonglong2*>((arrRow) + 4);       \
    (A)[0] = ffma2(_r0.x, (w2), (A)[0]);                                       \
    (A)[1] = ffma2(_r0.y, (w2), (A)[1]);                                       \
    (A)[2] = ffma2(_r1.x, (w2), (A)[2]);                                       \
    (A)[3] = ffma2(_r1.y, (w2), (A)[3]);                                       \
  } while (0)

__global__ void zero_kernel(int N) {
  size_t i = (size_t)blockIdx.x * blockDim.x + threadIdx.x;
  size_t stride = (size_t)gridDim.x * blockDim.x;
  float4 z = make_float4(0.f, 0.f, 0.f, 0.f);
  size_t n_s = (size_t)N * 64 / 4;
  for (size_t t = i; t < n_s; t += stride) reinterpret_cast<float4*>(g_agg_s)[t] = z;
  size_t n_v = (size_t)N * 192 / 4;
  for (size_t t = i; t < n_v; t += stride) reinterpret_cast<float4*>(g_agg_v)[t] = z;
}

// ---------------------------------------------------------------------------
// Edge kernel: fused gather -> gated TP m1 -> gated TP m2 -> atomic aggregate
// 8 edges per CTA, 128 threads, data transposed [k][edge] for f32x2 pairs.
// ---------------------------------------------------------------------------
__global__ void __launch_bounds__(128, 1) edge_kernel(
    const float* __restrict__ node_s, const float* __restrict__ node_v,
    const float* __restrict__ eas, const float* __restrict__ eav,
    const float* __restrict__ add_feat,
    const float* __restrict__ Wss1, const float* __restrict__ Wvs1,
    const float* __restrict__ Wsv1, const float* __restrict__ Wvv1,
    const float* __restrict__ b1,
    const float* __restrict__ Wss2, const float* __restrict__ Wvs2,
    const float* __restrict__ Wsv2, const float* __restrict__ Wvv2,
    const float* __restrict__ b2,
    const int* __restrict__ senders, const int* __restrict__ receivers,
    int E)
{
  __shared__ __align__(16) float xs_rT[130][TE];    // raw xs (for Wsv path)
  __shared__ __align__(16) float xs_aT[130][TE];    // xs * a_s (for Wss path)
  __shared__ __align__(16) float d1T[128][TE];      // (xv . av)/sqrt3
  __shared__ __align__(16) float xvaT[128][3][TE];  // xv raw, then xv * a_s
  __shared__ __align__(16) float ms_rT[64][TE];
  __shared__ __align__(16) float ms_aT[64][TE];
  __shared__ __align__(16) float gT[64][TE];        // gates (reused m1 then m2)
  __shared__ __align__(16) float d2T[64][TE];
  __shared__ __align__(16) float mvaT[64][3][TE];   // mv raw, then mv * a_s
  __shared__ __align__(16) float pT[64][TE];        // xs @ Wsv exchange
  __shared__ float asx[TE];
  __shared__ float avx[3][TE];
  __shared__ int sndx[TE], rcvx[TE];

  const int tid = threadIdx.x;
  const int e0 = blockIdx.x * TE;

  if (tid < TE) {
    int ge = e0 + tid;
    bool val = ge < E;
    sndx[tid] = val ? senders[ge] : 0;
    rcvx[tid] = val ? receivers[ge] : -1;
    asx[tid]  = val ? eas[ge] : 0.f;
#pragma unroll
    for (int i = 0; i < 3; i++) avx[i][tid] = val ? eav[ge * 3 + i] : 0.f;
  }
  __syncthreads();

  // gather xs = [node_s[snd] | node_s[rcv] | add_feat]
  for (int idx = tid; idx < TE * 130; idx += 128) {
    int e = idx / 130, s = idx - e * 130;
    int r = rcvx[e] < 0 ? 0 : rcvx[e];
    float v;
    if (s < 64)       v = __ldg(node_s + (size_t)sndx[e] * 64 + s);
    else if (s < 128) v = __ldg(node_s + (size_t)r * 64 + (s - 64));
    else {
      int ge = e0 + e;
      v = (ge < E) ? __ldg(add_feat + (size_t)ge * 2 + (s - 128)) : 0.f;
    }
    xs_rT[s][e] = v;
    xs_aT[s][e] = v * asx[e];
  }
  // gather xv = [node_v[snd] | node_v[rcv]] (raw for now)
  for (int idx = tid; idx < TE * 384; idx += 128) {
    int e = idx / 384, j = idx - e * 384;
    int r = rcvx[e] < 0 ? 0 : rcvx[e];
    float v = (j < 192) ? __ldg(node_v + (size_t)sndx[e] * 192 + j)
                        : __ldg(node_v + (size_t)r * 192 + (j - 192));
    xvaT[j / 3][j % 3][e] = v;
  }
  __syncthreads();

  // d1 = (xv . av)/sqrt3 ; xva = xv * a_s
  for (int t = tid; t < TE * 128; t += 128) {
    int v = t >> 3, e = t & 7;
    float r0 = xvaT[v][0][e], r1 = xvaT[v][1][e], r2 = xvaT[v][2][e];
    d1T[v][e] = (r0 * avx[0][e] + r1 * avx[1][e] + r2 * avx[2][e]) * RSQRT3;
    float a = asx[e];
    xvaT[v][0][e] = r0 * a; xvaT[v][1][e] = r1 * a; xvaT[v][2][e] = r2 * a;
  }
  __syncthreads();

  // ---- m1 scalar channels: s1[o] = (xs*a_s)@Wss1 + d1@Wvs1 ----
  {
    const int o = tid;
    ull acc[4] = {0, 0, 0, 0};
#pragma unroll 2
    for (int k = 0; k < 130; k++) {
      ull w2 = pack2(__ldg(Wss1 + k * 128 + o));
      ACC4(xs_aT[k], w2, acc);
    }
#pragma unroll 4
    for (int k = 0; k < 128; k++) {
      ull w2 = pack2(__ldg(Wvs1 + k * 128 + o));
      ACC4(d1T[k], w2, acc);
    }
    float sv[8]; upk8(acc, sv);
    float bo = __ldg(b1 + o);
    if (o < 64) {
#pragma unroll
      for (int e = 0; e < TE; e++) {
        float s1 = sv[e] * INV1 + bo;
        float m = s1 * sigm(s1);           // silu
        ms_rT[o][e] = m;
        ms_aT[o][e] = m * asx[e];
      }
    } else {
#pragma unroll
      for (int e = 0; e < TE; e++) {
        float s1 = sv[e] * INV1 + bo;
        gT[o - 64][e] = sigm(s1);          // gate
      }
    }
  }
  __syncthreads();

  // ---- m1 vector channels ----
  {
    const int o = tid & 63;
    ull accA[4] = {0, 0, 0, 0}, accB[4] = {0, 0, 0, 0};
    if (tid < 64) {          // role A: components i=0,1 of q = (xv*a_s)@Wvv1
#pragma unroll 2
      for (int k = 0; k < 128; k++) {
        ull w2 = pack2(__ldg(Wvv1 + k * 64 + o));
        ACC4(xvaT[k][0], w2, accA);
        ACC4(xvaT[k][1], w2, accB);
      }
    } else {                 // role B: component i=2 of q, plus p = xs@Wsv1
#pragma unroll 4
      for (int k = 0; k < 128; k++) {
        ull w2 = pack2(__ldg(Wvv1 + k * 64 + o));
        ACC4(xvaT[k][2], w2, accA);
      }
#pragma unroll 2
      for (int k = 0; k < 130; k++) {
        ull w2 = pack2(__ldg(Wsv1 + k * 64 + o));
        ACC4(xs_rT[k], w2, accB);
      }
      float pf[8]; upk8(accB, pf);
#pragma unroll
      for (int e = 0; e < TE; e++) pT[o][e] = pf[e];
    }
    __syncthreads();
    float qa[8], qb[8];
    upk8(accA, qa); upk8(accB, qb);
    if (tid < 64) {
#pragma unroll
      for (int e = 0; e < TE; e++) {
        float gi = gT[o][e] * INV1;
        float p = pT[o][e];
        mvaT[o][0][e] = (qa[e] + p * avx[0][e]) * gi;
        mvaT[o][1][e] = (qb[e] + p * avx[1][e]) * gi;
      }
    } else {
#pragma unroll
      for (int e = 0; e < TE; e++) {
        float gi = gT[o][e] * INV1;
        mvaT[o][2][e] = (qa[e] + qb[e] * avx[2][e]) * gi;
      }
    }
  }
  __syncthreads();

  // d2 = (mv . av)/sqrt3 ; mva = mv * a_s
  for (int t = tid; t < TE * 64; t += 128) {
    int v = t >> 3, e = t & 7;
    float r0 = mvaT[v][0][e], r1 = mvaT[v][1][e], r2 = mvaT[v][2][e];
    d2T[v][e] = (r0 * avx[0][e] + r1 * avx[1][e] + r2 * avx[2][e]) * RSQRT3;
    float a = asx[e];
    mvaT[v][0][e] = r0 * a; mvaT[v][1][e] = r1 * a; mvaT[v][2][e] = r2 * a;
  }
  __syncthreads();

  // ---- m2 scalar channels (+ atomic scatter of silu part) ----
  {
    const int o = tid;
    ull acc[4] = {0, 0, 0, 0};
#pragma unroll 4
    for (int k = 0; k < 64; k++) {
      ull w2 = pack2(__ldg(Wss2 + k * 128 + o));
      ACC4(ms_aT[k], w2, acc);
    }
#pragma unroll 4
    for (int k = 0; k < 64; k++) {
      ull w2 = pack2(__ldg(Wvs2 + k * 128 + o));
      ACC4(d2T[k], w2, acc);
    }
    float sv[8]; upk8(acc, sv);
    float bo = __ldg(b2 + o);
    if (o < 64) {
#pragma unroll
      for (int e = 0; e < TE; e++) {
        float s2 = sv[e] * INV2 + bo;
        float m = s2 * sigm(s2);
        int r = rcvx[e];
        if (r >= 0) atomicAdd(g_agg_s + (size_t)r * 64 + o, m);
      }
    } else {
#pragma unroll
      for (int e = 0; e < TE; e++) {
        gT[o - 64][e] = sigm(sv[e] * INV2 + bo);
      }
    }
  }
  __syncthreads();

  // ---- m2 vector channels (+ atomic scatter) ----
  {
    const int o = tid & 63;
    ull accA[4] = {0, 0, 0, 0}, accB[4] = {0, 0, 0, 0};
    if (tid < 64) {
#pragma unroll 2
      for (int k = 0; k < 64; k++) {
        ull w2 = pack2(__ldg(Wvv2 + k * 64 + o));
        ACC4(mvaT[k][0], w2, accA);
        ACC4(mvaT[k][1], w2, accB);
      }
    } else {
#pragma unroll 4
      for (int k = 0; k < 64; k++) {
        ull w2 = pack2(__ldg(Wvv2 + k * 64 + o));
        ACC4(mvaT[k][2], w2, accA);
      }
#pragma unroll 4
      for (int k = 0; k < 64; k++) {
        ull w2 = pack2(__ldg(Wsv2 + k * 64 + o));
        ACC4(ms_rT[k], w2, accB);
      }
      float pf[8]; upk8(accB, pf);
#pragma unroll
      for (int e = 0; e < TE; e++) pT[o][e] = pf[e];
    }
    __syncthreads();
    float qa[8], qb[8];
    upk8(accA, qa); upk8(accB, qb);
    if (tid < 64) {
#pragma unroll
      for (int e = 0; e < TE; e++) {
        int r = rcvx[e];
        if (r < 0) continue;
        float gi = gT[o][e] * INV2;
        float p = pT[o][e];
        atomicAdd(g_agg_v + (size_t)r * 192 + o * 3 + 0, (qa[e] + p * avx[0][e]) * gi);
        atomicAdd(g_agg_v + (size_t)r * 192 + o * 3 + 1, (qb[e] + p * avx[1][e]) * gi);
      }
    } else {
#pragma unroll
      for (int e = 0; e < TE; e++) {
        int r = rcvx[e];
        if (r < 0) continue;
        float gi = gT[o][e] * INV2;
        atomicAdd(g_agg_v + (size_t)r * 192 + o * 3 + 2, (qa[e] + qb[e] * avx[2][e]) * gi);
      }
    }
  }
}

// ---------------------------------------------------------------------------
// Node kernel: fused [node | agg] -> gated TP u0 -> TP u1 -> residual + output
// ---------------------------------------------------------------------------
__global__ void __launch_bounds__(128, 1) node_kernel(
    const float* __restrict__ node_s, const float* __restrict__ node_v,
    const float* __restrict__ nas, const float* __restrict__ nav,
    const float* __restrict__ Wss0, const float* __restrict__ Wvs0,
    const float* __restrict__ Wsv0, const float* __restrict__ Wvv0,
    const float* __restrict__ b0,
    const float* __restrict__ Wssu, const float* __restrict__ Wvsu,
    const float* __restrict__ Wsvu, const float* __restrict__ Wvvu,
    const float* __restrict__ bu,
    float* __restrict__ out, int N)
{
  __shared__ __align__(16) float xs_rT[128][TE];
  __shared__ __align__(16) float xs_aT[128][TE];
  __shared__ __align__(16) float d1T[128][TE];
  __shared__ __align__(16) float xvaT[128][3][TE];
  __shared__ __align__(16) float hs_rT[64][TE];
  __shared__ __align__(16) float hs_aT[64][TE];
  __shared__ __align__(16) float gT[64][TE];
  __shared__ __align__(16) float d2T[64][TE];
  __shared__ __align__(16) float hvaT[64][3][TE];
  __shared__ __align__(16) float pT[64][TE];
  __shared__ float asx[TE], avx[3][TE];

  const int tid = threadIdx.x;
  const int n0 = blockIdx.x * TE;

  if (tid < TE) {
    int n = n0 + tid;
    bool val = n < N;
    asx[tid] = val ? nas[n] : 0.f;
#pragma unroll
    for (int i = 0; i < 3; i++) avx[i][tid] = val ? nav[n * 3 + i] : 0.f;
  }
  __syncthreads();

  for (int idx = tid; idx < TE * 128; idx += 128) {
    int e = idx >> 7, s = idx & 127;
    int n = n0 + e; if (n >= N) n = 0;
    float v = (s < 64) ? __ldg(node_s + (size_t)n * 64 + s)
                       : g_agg_s[(size_t)n * 64 + (s - 64)];
    xs_rT[s][e] = v;
    xs_aT[s][e] = v * asx[e];
  }
  for (int idx = tid; idx < TE * 384; idx += 128) {
    int e = idx / 384, j = idx - e * 384;
    int n = n0 + e; if (n >= N) n = 0;
    float v = (j < 192) ? __ldg(node_v + (size_t)n * 192 + j)
                        : g_agg_v[(size_t)n * 192 + (j - 192)];
    xvaT[j / 3][j % 3][e] = v;
  }
  __syncthreads();

  for (int t = tid; t < TE * 128; t += 128) {
    int v = t >> 3, e = t & 7;
    float r0 = xvaT[v][0][e], r1 = xvaT[v][1][e], r2 = xvaT[v][2][e];
    d1T[v][e] = (r0 * avx[0][e] + r1 * avx[1][e] + r2 * avx[2][e]) * RSQRT3;
    float a = asx[e];
    xvaT[v][0][e] = r0 * a; xvaT[v][1][e] = r1 * a; xvaT[v][2][e] = r2 * a;
  }
  __syncthreads();

  // ---- u0 scalar ----
  {
    const int o = tid;
    ull acc[4] = {0, 0, 0, 0};
#pragma unroll 4
    for (int k = 0; k < 128; k++) {
      ull w2 = pack2(__ldg(Wss0 + k * 128 + o));
      ACC4(xs_aT[k], w2, acc);
    }
#pragma unroll 4
    for (int k = 0; k < 128; k++) {
      ull w2 = pack2(__ldg(Wvs0 + k * 128 + o));
      ACC4(d1T[k], w2, acc);
    }
    float sv[8]; upk8(acc, sv);
    float bo = __ldg(b0 + o);
    if (o < 64) {
#pragma unroll
      for (int e = 0; e < TE; e++) {
        float s1 = sv[e] * INV0 + bo;
        float m = s1 * sigm(s1);
        hs_rT[o][e] = m;
        hs_aT[o][e] = m * asx[e];
      }
    } else {
#pragma unroll
      for (int e = 0; e < TE; e++) {
        gT[o - 64][e] = sigm(sv[e] * INV0 + bo);
      }
    }
  }
  __syncthreads();

  // ---- u0 vector ----
  {
    const int o = tid & 63;
    ull accA[4] = {0, 0, 0, 0}, accB[4] = {0, 0, 0, 0};
    if (tid < 64) {
#pragma unroll 2
      for (int k = 0; k < 128; k++) {
        ull w2 = pack2(__ldg(Wvv0 + k * 64 + o));
        ACC4(xvaT[k][0], w2, accA);
        ACC4(xvaT[k][1], w2, accB);
      }
    } else {
#pragma unroll 4
      for (int k = 0; k < 128; k++) {
        ull w2 = pack2(__ldg(Wvv0 + k * 64 + o));
        ACC4(xvaT[k][2], w2, accA);
      }
#pragma unroll 4
      for (int k = 0; k < 128; k++) {
        ull w2 = pack2(__ldg(Wsv0 + k * 64 + o));
        ACC4(xs_rT[k], w2, accB);
      }
      float pf[8]; upk8(accB, pf);
#pragma unroll
      for (int e = 0; e < TE; e++) pT[o][e] = pf[e];
    }
    __syncthreads();
    float qa[8], qb[8];
    upk8(accA, qa); upk8(accB, qb);
    if (tid < 64) {
#pragma unroll
      for (int e = 0; e < TE; e++) {
        float gi = gT[o][e] * INV0;
        float p = pT[o][e];
        hvaT[o][0][e] = (qa[e] + p * avx[0][e]) * gi;
        hvaT[o][1][e] = (qb[e] + p * avx[1][e]) * gi;
      }
    } else {
#pragma unroll
      for (int e = 0; e < TE; e++) {
        float gi = gT[o][e] * INV0;
        hvaT[o][2][e] = (qa[e] + qb[e] * avx[2][e]) * gi;
      }
    }
  }
  __syncthreads();

  for (int t = tid; t < TE * 64; t += 128) {
    int v = t >> 3, e = t & 7;
    float r0 = hvaT[v][0][e], r1 = hvaT[v][1][e], r2 = hvaT[v][2][e];
    d2T[v][e] = (r0 * avx[0][e] + r1 * avx[1][e] + r2 * avx[2][e]) * RSQRT3;
    float a = asx[e];
    hvaT[v][0][e] = r0 * a; hvaT[v][1][e] = r1 * a; hvaT[v][2][e] = r2 * a;
  }
  __syncthreads();

  // ---- u1 scalar (64 outputs, no gate) + residual write ----
  if (tid < 64) {
    const int o = tid;
    ull acc[4] = {0, 0, 0, 0};
#pragma unroll 4
    for (int k = 0; k < 64; k++) {
      ull w2 = pack2(__ldg(Wssu + k * 64 + o));
      ACC4(hs_aT[k], w2, acc);
    }
#pragma unroll 4
    for (int k = 0; k < 64; k++) {
      ull w2 = pack2(__ldg(Wvsu + k * 64 + o));
      ACC4(d2T[k], w2, acc);
    }
    float sv[8]; upk8(acc, sv);
    float bo = __ldg(bu + o);
#pragma unroll
    for (int e = 0; e < TE; e++) {
      int n = n0 + e;
      if (n < N)
        out[(size_t)n * 256 + o] =
            __ldg(node_s + (size_t)n * 64 + o) + sv[e] * INVU + bo;
    }
  }

  // ---- u1 vector (no gate) + residual write ----
  {
    const int o = tid & 63;
    ull accA[4] = {0, 0, 0, 0}, accB[4] = {0, 0, 0, 0};
    if (tid < 64) {
#pragma unroll 2
      for (int k = 0; k < 64; k++) {
        ull w2 = pack2(__ldg(Wvvu + k * 64 + o));
        ACC4(hvaT[k][0], w2, accA);
        ACC4(hvaT[k][1], w2, accB);
      }
    } else {
#pragma unroll 4
      for (int k = 0; k < 64; k++) {
        ull w2 = pack2(__ldg(Wvvu + k * 64 + o));
        ACC4(hvaT[k][2], w2, accA);
      }
#pragma unroll 4
      for (int k = 0; k < 64; k++) {
        ull w2 = pack2(__ldg(Wsvu + k * 64 + o));
        ACC4(hs_rT[k], w2, accB);
      }
      float pf[8]; upk8(accB, pf);
#pragma unroll
      for (int e = 0; e < TE; e++) pT[o][e] = pf[e];
    }
    __syncthreads();
    float qa[8], qb[8];
    upk8(accA, qa); upk8(accB, qb);
    if (tid < 64) {
#pragma unroll
      for (int e = 0; e < TE; e++) {
        int n = n0 + e;
        if (n >= N) continue;
        float p = pT[o][e];
        out[(size_t)n * 256 + 64 + o * 3 + 0] =
            __ldg(node_v + (size_t)n * 192 + o * 3 + 0) + (qa[e] + p * avx[0][e]) * INVU;
        out[(size_t)n * 256 + 64 + o * 3 + 1] =
            __ldg(node_v + (size_t)n * 192 + o * 3 + 1) + (qb[e] + p * avx[1][e]) * INVU;
      }
    } else {
#pragma unroll
      for (int e = 0; e < TE; e++) {
        int n = n0 + e;
        if (n >= N) continue;
        out[(size_t)n * 256 + 64 + o * 3 + 2] =
            __ldg(node_v + (size_t)n * 192 + o * 3 + 2) + (qa[e] + qb[e] * avx[2][e]) * INVU;
      }
    }
  }
}

extern "C" void kernel_launch(void* const* d_in, const int* in_sizes, int n_in,
                              void* d_out, int out_size) {
  const float* node_s = (const float*)d_in[0];
  const float* node_v = (const float*)d_in[1];
  const float* nas    = (const float*)d_in[2];
  const float* nav    = (const float*)d_in[3];
  const float* eas    = (const float*)d_in[4];
  const float* eav    = (const float*)d_in[5];
  const float* add_f  = (const float*)d_in[6];
  const float* m1Wss  = (const float*)d_in[7];
  const float* m1Wvs  = (const float*)d_in[8];
  const float* m1Wsv  = (const float*)d_in[9];
  const float* m1Wvv  = (const float*)d_in[10];
  const float* m1b    = (const float*)d_in[11];
  const float* m2Wss  = (const float*)d_in[12];
  const float* m2Wvs  = (const float*)d_in[13];
  const float* m2Wsv  = (const float*)d_in[14];
  const float* m2Wvv  = (const float*)d_in[15];
  const float* m2b    = (const float*)d_in[16];
  const float* u0Wss  = (const float*)d_in[17];
  const float* u0Wvs  = (const float*)d_in[18];
  const float* u0Wsv  = (const float*)d_in[19];
  const float* u0Wvv  = (const float*)d_in[20];
  const float* u0b    = (const float*)d_in[21];
  const float* u1Wss  = (const float*)d_in[22];
  const float* u1Wvs  = (const float*)d_in[23];
  const float* u1Wsv  = (const float*)d_in[24];
  const float* u1Wvv  = (const float*)d_in[25];
  const float* u1b    = (const float*)d_in[26];
  const int* senders   = (const int*)d_in[27];
  const int* receivers = (const int*)d_in[28];

  int E = in_sizes[27];
  int N = in_sizes[0] / 64;

  zero_kernel<<<512, 256>>>(N);
  edge_kernel<<<(E + TE - 1) / TE, 128>>>(
      node_s, node_v, eas, eav, add_f,
      m1Wss, m1Wvs, m1Wsv, m1Wvv, m1b,
      m2Wss, m2Wvs, m2Wsv, m2Wvv, m2b,
      senders, receivers, E);
  node_kernel<<<(N + TE - 1) / TE, 128>>>(
      node_s, node_v, nas, nav,
      u0Wss, u0Wvs, u0Wsv, u0Wvv, u0b,
      u1Wss, u1Wvs, u1Wsv, u1Wvv, u1b,
      (float*)d_out, N);
}